// round 2
// baseline (speedup 1.0000x reference)
#include <cuda_runtime.h>
#include <math.h>

#define BB 64
#define SS 512
#define II 512
#define HH 1024
#define OO 512
#define G4 4096

// ---------------- scratch (device globals; no allocation APIs) ----------------
__device__ float g_xW[(size_t)SS * BB * G4];   // [t][b][4096] : x-part of gates + bias
__device__ float g_hs[(size_t)SS * BB * HH];   // [t][b][1024] : h history
__device__ float g_h[2][BB * HH];              // ping-pong h
__device__ float g_c[2][BB * HH];              // ping-pong c
__device__ float g_Wrec[128 * 1024 * 32];      // [jt][k][c], c = g*8 + jj

// ---------------- helpers ----------------
__device__ __forceinline__ float sigmoid_f(float x) {
    return 1.0f / (1.0f + expf(-x));
}
__device__ __forceinline__ float tanh_f(float x) {
    // 2*sigmoid(2x)-1 : uses only expf (accurate even under fast-math)
    return 2.0f / (1.0f + expf(-2.0f * x)) - 1.0f;
}

// ---------------- repack recurrent weights: W_g[k][j] -> g_Wrec[jt][k][g*8+jj] ----------------
__global__ void repack_kernel(const float* __restrict__ Wf, const float* __restrict__ Wi,
                              const float* __restrict__ Wo, const float* __restrict__ Wc) {
    int idx = blockIdx.x * blockDim.x + threadIdx.x;
    if (idx >= 128 * 1024 * 32) return;
    int c  = idx & 31;
    int k  = (idx >> 5) & 1023;
    int jt = idx >> 15;
    int g  = c >> 3;
    int j  = jt * 8 + (c & 7);
    const float* W = (g == 0) ? Wf : (g == 1) ? Wi : (g == 2) ? Wo : Wc;
    g_Wrec[idx] = W[(size_t)k * HH + j];
}

// ---------------- init h/c buffers ----------------
__global__ void init_kernel(const float* __restrict__ h0, const float* __restrict__ c0) {
    int i = blockIdx.x * blockDim.x + threadIdx.x;
    if (i < BB * HH) {
        g_h[0][i] = h0[i];
        g_c[0][i] = c0[i];
    }
}

// ---------------- precompute x-contribution to gates: one big GEMM ----------------
// g_xW[t][b][n] = sum_k x[b][t][k] * W_g[1024+k][j] + bias_g[j],  n = g*1024+j
// grid: (64 n-tiles, 512 t)  block: 256 threads, 64x64 tile, BK=16, 4x4/thread
__global__ __launch_bounds__(256) void xw_kernel(
    const float* __restrict__ x,
    const float* __restrict__ Wf, const float* __restrict__ bf,
    const float* __restrict__ Wi, const float* __restrict__ bi,
    const float* __restrict__ Wo, const float* __restrict__ bo,
    const float* __restrict__ Wc, const float* __restrict__ bc) {
    __shared__ float As[16][64];   // [k][b]
    __shared__ float Bs[16][64];   // [k][n]
    int nt = blockIdx.x;           // 0..63
    int t  = blockIdx.y;           // 0..511
    int n0 = nt * 64;
    int g  = n0 >> 10;
    int j0 = n0 & (HH - 1);
    const float* W    = (g == 0) ? Wf : (g == 1) ? Wi : (g == 2) ? Wo : Wc;
    const float* bias = (g == 0) ? bf : (g == 1) ? bi : (g == 2) ? bo : bc;

    int tid = threadIdx.x;
    int tx = tid & 15, ty = tid >> 4;
    int ar = tid >> 2;            // b-row 0..63
    int ak = (tid & 3) * 4;       // k offset
    int br = tid >> 4;            // 0..15
    int bc4 = (tid & 15) * 4;
    const float* xrow = x + (size_t)ar * (SS * II) + (size_t)t * II;

    float acc[4][4] = {};
    for (int k0 = 0; k0 < II; k0 += 16) {
        float4 av = *(const float4*)(xrow + k0 + ak);
        As[ak + 0][ar] = av.x; As[ak + 1][ar] = av.y;
        As[ak + 2][ar] = av.z; As[ak + 3][ar] = av.w;
        float4 bv = *(const float4*)(W + (size_t)(HH + k0 + br) * HH + j0 + bc4);
        *(float4*)&Bs[br][bc4] = bv;
        __syncthreads();
#pragma unroll
        for (int kk = 0; kk < 16; kk++) {
            float4 a = *(const float4*)&As[kk][ty * 4];
            float4 b = *(const float4*)&Bs[kk][tx * 4];
            float ae[4] = {a.x, a.y, a.z, a.w};
            float be[4] = {b.x, b.y, b.z, b.w};
#pragma unroll
            for (int um = 0; um < 4; um++)
#pragma unroll
                for (int un = 0; un < 4; un++)
                    acc[um][un] += ae[um] * be[un];
        }
        __syncthreads();
    }
    float4 bb = *(const float4*)(bias + j0 + tx * 4);
#pragma unroll
    for (int um = 0; um < 4; um++) {
        int m = t * 64 + ty * 4 + um;   // [t][b]
        float4 v;
        v.x = acc[um][0] + bb.x; v.y = acc[um][1] + bb.y;
        v.z = acc[um][2] + bb.z; v.w = acc[um][3] + bb.w;
        *(float4*)&g_xW[(size_t)m * G4 + n0 + tx * 4] = v;
    }
}

// ---------------- one LSTM timestep ----------------
// grid: 128 blocks (each owns 8 hidden cols x 4 gates), 128 threads
// GEMM: [64 x 32] = h_prev[64 x 1024] @ Wrec_tile[1024 x 32], then fused LSTM update
__global__ __launch_bounds__(128) void step_kernel(int t) {
    __shared__ float As[16][64];   // [k][b]
    __shared__ float Bs[16][32];   // [k][c]
    __shared__ float gt[64][33];   // staged gate pre-activations (padded)
    int jt = blockIdx.x;
    int pb = t & 1, nb = pb ^ 1;
    int tid = threadIdx.x;
    int tx = tid & 7, ty = tid >> 3;
    int ar = tid >> 1;            // 0..63
    int ak = (tid & 1) * 8;       // 0 or 8
    int br = tid >> 3;            // 0..15
    int bc4 = (tid & 7) * 4;
    const float* hprev = g_h[pb];
    const float* Wr = g_Wrec + (size_t)jt * 1024 * 32;

    float acc[4][4] = {};
    for (int k0 = 0; k0 < HH; k0 += 16) {
        const float* hp = hprev + (size_t)ar * HH + k0 + ak;
        float4 a0 = *(const float4*)(hp);
        float4 a1 = *(const float4*)(hp + 4);
        As[ak + 0][ar] = a0.x; As[ak + 1][ar] = a0.y;
        As[ak + 2][ar] = a0.z; As[ak + 3][ar] = a0.w;
        As[ak + 4][ar] = a1.x; As[ak + 5][ar] = a1.y;
        As[ak + 6][ar] = a1.z; As[ak + 7][ar] = a1.w;
        float4 bv = *(const float4*)(Wr + (size_t)(k0 + br) * 32 + bc4);
        *(float4*)&Bs[br][bc4] = bv;
        __syncthreads();
#pragma unroll
        for (int kk = 0; kk < 16; kk++) {
            float4 a = *(const float4*)&As[kk][ty * 4];
            float4 b = *(const float4*)&Bs[kk][tx * 4];
            float ae[4] = {a.x, a.y, a.z, a.w};
            float be[4] = {b.x, b.y, b.z, b.w};
#pragma unroll
            for (int um = 0; um < 4; um++)
#pragma unroll
                for (int un = 0; un < 4; un++)
                    acc[um][un] += ae[um] * be[un];
        }
        __syncthreads();
    }
    // stage gate pre-activations
#pragma unroll
    for (int um = 0; um < 4; um++)
#pragma unroll
        for (int un = 0; un < 4; un++)
            gt[ty * 4 + um][tx * 4 + un] = acc[um][un];
    __syncthreads();

    int j0 = jt * 8;
    for (int it = tid; it < 512; it += 128) {
        int b = it >> 3, jj = it & 7;
        const float* xw = &g_xW[(size_t)(t * 64 + b) * G4 + j0 + jj];
        float pf = gt[b][jj]      + xw[0];
        float pi = gt[b][8 + jj]  + xw[1024];
        float po = gt[b][16 + jj] + xw[2048];
        float pc = gt[b][24 + jj] + xw[3072];
        float f  = sigmoid_f(pf);
        float i2 = sigmoid_f(pi);
        float o  = sigmoid_f(po);
        float ct = tanh_f(pc);
        int hidx = b * HH + j0 + jj;
        float cnew = f * g_c[pb][hidx] + i2 * ct;
        float hnew = o * tanh_f(cnew);
        g_c[nb][hidx] = cnew;
        g_h[nb][hidx] = hnew;
        g_hs[(size_t)(t * 64 + b) * HH + j0 + jj] = hnew;
    }
}

// ---------------- output projection: out[b][s][o] = hs[s][b][:] @ W_hy + b_hy ----------------
// grid: (8 n-tiles, 512 s), 256 threads, 64x64 tile, BK=16
__global__ __launch_bounds__(256) void proj_kernel(const float* __restrict__ Why,
                                                   const float* __restrict__ bhy,
                                                   float* __restrict__ out) {
    __shared__ float As[16][64];
    __shared__ float Bs[16][64];
    int nt = blockIdx.x;   // 0..7
    int s  = blockIdx.y;   // 0..511
    int n0 = nt * 64;
    int tid = threadIdx.x;
    int tx = tid & 15, ty = tid >> 4;
    int ar = tid >> 2;
    int ak = (tid & 3) * 4;
    int br = tid >> 4;
    int bc4 = (tid & 15) * 4;
    const float* arow = g_hs + (size_t)(s * 64 + ar) * HH;

    float acc[4][4] = {};
    for (int k0 = 0; k0 < HH; k0 += 16) {
        float4 av = *(const float4*)(arow + k0 + ak);
        As[ak + 0][ar] = av.x; As[ak + 1][ar] = av.y;
        As[ak + 2][ar] = av.z; As[ak + 3][ar] = av.w;
        float4 bv = *(const float4*)(Why + (size_t)(k0 + br) * OO + n0 + bc4);
        *(float4*)&Bs[br][bc4] = bv;
        __syncthreads();
#pragma unroll
        for (int kk = 0; kk < 16; kk++) {
            float4 a = *(const float4*)&As[kk][ty * 4];
            float4 b = *(const float4*)&Bs[kk][tx * 4];
            float ae[4] = {a.x, a.y, a.z, a.w};
            float be[4] = {b.x, b.y, b.z, b.w};
#pragma unroll
            for (int um = 0; um < 4; um++)
#pragma unroll
                for (int un = 0; un < 4; un++)
                    acc[um][un] += ae[um] * be[un];
        }
        __syncthreads();
    }
    float4 bb = *(const float4*)(bhy + n0 + tx * 4);
#pragma unroll
    for (int um = 0; um < 4; um++) {
        int b = ty * 4 + um;
        float4 v;
        v.x = acc[um][0] + bb.x; v.y = acc[um][1] + bb.y;
        v.z = acc[um][2] + bb.z; v.w = acc[um][3] + bb.w;
        *(float4*)&out[(size_t)b * (SS * OO) + (size_t)s * OO + n0 + tx * 4] = v;
    }
}

// ---------------- copy final h, c into tail of output ----------------
__global__ void finalize_kernel(float* __restrict__ out) {
    int i = blockIdx.x * blockDim.x + threadIdx.x;
    const size_t base = (size_t)BB * SS * OO;   // 16777216
    if (i < BB * HH) {
        out[base + i]            = g_h[0][i];   // after 512 steps, state lives in buffer 0
        out[base + BB * HH + i]  = g_c[0][i];
    }
}

// ---------------- launch ----------------
extern "C" void kernel_launch(void* const* d_in, const int* in_sizes, int n_in,
                              void* d_out, int out_size) {
    const float* x   = (const float*)d_in[0];
    const float* h0  = (const float*)d_in[1];
    const float* c0  = (const float*)d_in[2];
    const float* Wf  = (const float*)d_in[3];
    const float* bf  = (const float*)d_in[4];
    const float* Wi  = (const float*)d_in[5];
    const float* bi  = (const float*)d_in[6];
    const float* Wo  = (const float*)d_in[7];
    const float* bo  = (const float*)d_in[8];
    const float* Wc  = (const float*)d_in[9];
    const float* bc  = (const float*)d_in[10];
    const float* Why = (const float*)d_in[11];
    const float* bhy = (const float*)d_in[12];
    float* out = (float*)d_out;

    repack_kernel<<<(128 * 1024 * 32 + 255) / 256, 256>>>(Wf, Wi, Wo, Wc);
    init_kernel<<<(BB * HH + 255) / 256, 256>>>(h0, c0);
    xw_kernel<<<dim3(64, 512), 256>>>(x, Wf, bf, Wi, bi, Wo, bo, Wc, bc);
    for (int t = 0; t < SS; t++) {
        step_kernel<<<128, 128>>>(t);
    }
    proj_kernel<<<dim3(8, 512), 256>>>(Why, bhy, out);
    finalize_kernel<<<(BB * HH + 255) / 256, 256>>>(out);
}

// round 3
// speedup vs baseline: 1.3062x; 1.3062x over previous
#include <cuda_runtime.h>
#include <math.h>

#define BB 64
#define SS 512
#define II 512
#define HH 1024
#define OO 512
#define G4 4096
#define NBLK 128

// ---------------- scratch (device globals; no allocation APIs) ----------------
__device__ float g_xW[(size_t)SS * BB * G4];   // [t][b][4096] : x-part of gates + bias
__device__ float g_hs[(size_t)SS * BB * HH];   // [t][b][1024] : h history
__device__ float g_h[2][BB * HH];              // ping-pong h
__device__ float g_c[2][BB * HH];              // ping-pong c
__device__ float g_Wrec[128 * 1024 * 32];      // [jt][k][c], c = g*8 + jj
__device__ unsigned int g_bar_arrive;          // grid barrier state
__device__ unsigned int g_bar_gen;

// ---------------- helpers ----------------
__device__ __forceinline__ float sigmoid_f(float x) {
    return 1.0f / (1.0f + expf(-x));
}
__device__ __forceinline__ float tanh_f(float x) {
    return 2.0f / (1.0f + expf(-2.0f * x)) - 1.0f;
}

// ---------------- repack recurrent weights: W_g[k][j] -> g_Wrec[jt][k][g*8+jj] ----------------
__global__ void repack_kernel(const float* __restrict__ Wf, const float* __restrict__ Wi,
                              const float* __restrict__ Wo, const float* __restrict__ Wc) {
    int idx = blockIdx.x * blockDim.x + threadIdx.x;
    if (idx >= 128 * 1024 * 32) return;
    int c  = idx & 31;
    int k  = (idx >> 5) & 1023;
    int jt = idx >> 15;
    int g  = c >> 3;
    int j  = jt * 8 + (c & 7);
    const float* W = (g == 0) ? Wf : (g == 1) ? Wi : (g == 2) ? Wo : Wc;
    g_Wrec[idx] = W[(size_t)k * HH + j];
}

// ---------------- init h/c buffers + barrier state ----------------
__global__ void init_kernel(const float* __restrict__ h0, const float* __restrict__ c0) {
    int i = blockIdx.x * blockDim.x + threadIdx.x;
    if (i < BB * HH) {
        g_h[0][i] = h0[i];
        g_c[0][i] = c0[i];
    }
    if (i == 0) {
        g_bar_arrive = 0u;
        g_bar_gen = 0u;
    }
}

// ---------------- precompute x-contribution to gates: one big GEMM ----------------
__global__ __launch_bounds__(256) void xw_kernel(
    const float* __restrict__ x,
    const float* __restrict__ Wf, const float* __restrict__ bf,
    const float* __restrict__ Wi, const float* __restrict__ bi,
    const float* __restrict__ Wo, const float* __restrict__ bo,
    const float* __restrict__ Wc, const float* __restrict__ bc) {
    __shared__ float As[16][64];   // [k][b]
    __shared__ float Bs[16][64];   // [k][n]
    int nt = blockIdx.x;           // 0..63
    int t  = blockIdx.y;           // 0..511
    int n0 = nt * 64;
    int g  = n0 >> 10;
    int j0 = n0 & (HH - 1);
    const float* W    = (g == 0) ? Wf : (g == 1) ? Wi : (g == 2) ? Wo : Wc;
    const float* bias = (g == 0) ? bf : (g == 1) ? bi : (g == 2) ? bo : bc;

    int tid = threadIdx.x;
    int tx = tid & 15, ty = tid >> 4;
    int ar = tid >> 2;
    int ak = (tid & 3) * 4;
    int br = tid >> 4;
    int bc4 = (tid & 15) * 4;
    const float* xrow = x + (size_t)ar * (SS * II) + (size_t)t * II;

    float acc[4][4] = {};
    for (int k0 = 0; k0 < II; k0 += 16) {
        float4 av = *(const float4*)(xrow + k0 + ak);
        As[ak + 0][ar] = av.x; As[ak + 1][ar] = av.y;
        As[ak + 2][ar] = av.z; As[ak + 3][ar] = av.w;
        float4 bv = *(const float4*)(W + (size_t)(HH + k0 + br) * HH + j0 + bc4);
        *(float4*)&Bs[br][bc4] = bv;
        __syncthreads();
#pragma unroll
        for (int kk = 0; kk < 16; kk++) {
            float4 a = *(const float4*)&As[kk][ty * 4];
            float4 b = *(const float4*)&Bs[kk][tx * 4];
            float ae[4] = {a.x, a.y, a.z, a.w};
            float be[4] = {b.x, b.y, b.z, b.w};
#pragma unroll
            for (int um = 0; um < 4; um++)
#pragma unroll
                for (int un = 0; un < 4; un++)
                    acc[um][un] += ae[um] * be[un];
        }
        __syncthreads();
    }
    float4 bb = *(const float4*)(bias + j0 + tx * 4);
#pragma unroll
    for (int um = 0; um < 4; um++) {
        int m = t * 64 + ty * 4 + um;   // [t][b]
        float4 v;
        v.x = acc[um][0] + bb.x; v.y = acc[um][1] + bb.y;
        v.z = acc[um][2] + bb.z; v.w = acc[um][3] + bb.w;
        *(float4*)&g_xW[(size_t)m * G4 + n0 + tx * 4] = v;
    }
}

// ---------------- grid-wide barrier (all NBLK blocks co-resident) ----------------
__device__ __forceinline__ void grid_barrier(unsigned int target) {
    __threadfence();            // release this thread's global writes
    __syncthreads();
    if (threadIdx.x == 0) {
        unsigned int old = atomicAdd(&g_bar_arrive, 1u);
        if (old == NBLK - 1) {
            atomicExch(&g_bar_arrive, 0u);
            __threadfence();
            atomicExch(&g_bar_gen, target);
        } else {
            while (atomicAdd(&g_bar_gen, 0u) < target) {
                __nanosleep(32);
            }
        }
    }
    __syncthreads();
}

// ---------------- persistent LSTM recurrence: all 512 steps in one kernel ----------------
// 128 blocks x 256 threads. Each block owns 8 hidden cols (x4 gates = 32 gate cols).
// Intra-block K-split: half z in {0,1} covers K rows [z*512, z*512+512).
// Per half: 128 threads compute the 64x32 tile with 4x4 register tiles,
// double-buffered smem + global prefetch.
__global__ __launch_bounds__(256) void lstm_persist_kernel() {
    __shared__ float As[2][2][16][64];   // [z][buf][k][b]
    __shared__ float Bs[2][2][16][32];   // [z][buf][k][c]
    __shared__ float gts[2][64][33];     // per-half partial gate pre-activations

    const int jt  = blockIdx.x;
    const int tid = threadIdx.x;
    const int z   = tid >> 7;            // K-half
    const int wt  = tid & 127;
    const int tx  = wt & 7;              // n/4
    const int ty  = wt >> 3;             // m/4
    const int ar  = wt >> 1;             // 0..63 (b row for A loads)
    const int ak  = (wt & 1) * 8;        // k offset within chunk for A loads
    const int br  = wt >> 3;             // 0..15 (k row for B loads)
    const int bc4 = (wt & 7) * 4;        // c offset for B loads
    const int kbase = z * 512;
    const float* Wr = g_Wrec + (size_t)jt * (1024 * 32);
    const int j0 = jt * 8;

    for (int t = 0; t < SS; t++) {
        const int pb = t & 1, nb = pb ^ 1;
        const float* hprev = g_h[pb];

        float acc[4][4] = {};
        // ---- prologue: load chunk 0 into regs, stage to smem buf 0 ----
        const float* hp = hprev + (size_t)ar * HH + kbase + ak;
        float4 a0 = __ldcg((const float4*)(hp));
        float4 a1 = __ldcg((const float4*)(hp + 4));
        float4 bv = __ldg((const float4*)(Wr + (size_t)(kbase + br) * 32 + bc4));
        As[z][0][ak + 0][ar] = a0.x; As[z][0][ak + 1][ar] = a0.y;
        As[z][0][ak + 2][ar] = a0.z; As[z][0][ak + 3][ar] = a0.w;
        As[z][0][ak + 4][ar] = a1.x; As[z][0][ak + 5][ar] = a1.y;
        As[z][0][ak + 6][ar] = a1.z; As[z][0][ak + 7][ar] = a1.w;
        *(float4*)&Bs[z][0][br][bc4] = bv;
        __syncthreads();

        int buf = 0;
        for (int ch = 0; ch < 32; ch++) {
            float4 na0, na1, nbv;
            if (ch < 31) {
                const int k0 = kbase + (ch + 1) * 16;
                const float* hp2 = hprev + (size_t)ar * HH + k0 + ak;
                na0 = __ldcg((const float4*)(hp2));
                na1 = __ldcg((const float4*)(hp2 + 4));
                nbv = __ldg((const float4*)(Wr + (size_t)(k0 + br) * 32 + bc4));
            }
#pragma unroll
            for (int kk = 0; kk < 16; kk++) {
                float4 a = *(const float4*)&As[z][buf][kk][ty * 4];
                float4 b = *(const float4*)&Bs[z][buf][kk][tx * 4];
                float ae[4] = {a.x, a.y, a.z, a.w};
                float be[4] = {b.x, b.y, b.z, b.w};
#pragma unroll
                for (int um = 0; um < 4; um++)
#pragma unroll
                    for (int un = 0; un < 4; un++)
                        acc[um][un] += ae[um] * be[un];
            }
            if (ch < 31) {
                const int nbuf = buf ^ 1;
                As[z][nbuf][ak + 0][ar] = na0.x; As[z][nbuf][ak + 1][ar] = na0.y;
                As[z][nbuf][ak + 2][ar] = na0.z; As[z][nbuf][ak + 3][ar] = na0.w;
                As[z][nbuf][ak + 4][ar] = na1.x; As[z][nbuf][ak + 5][ar] = na1.y;
                As[z][nbuf][ak + 6][ar] = na1.z; As[z][nbuf][ak + 7][ar] = na1.w;
                *(float4*)&Bs[z][nbuf][br][bc4] = nbv;
            }
            __syncthreads();
            buf ^= 1;
        }

        // ---- stage per-half partials ----
#pragma unroll
        for (int um = 0; um < 4; um++)
#pragma unroll
            for (int un = 0; un < 4; un++)
                gts[z][ty * 4 + um][tx * 4 + un] = acc[um][un];
        __syncthreads();

        // ---- fused LSTM elementwise over this block's 512 h-elements ----
        for (int it = tid; it < 512; it += 256) {
            const int b = it >> 3, jj = it & 7;
            const float* xw = &g_xW[(size_t)(t * 64 + b) * G4 + j0 + jj];
            float pf = gts[0][b][jj]      + gts[1][b][jj]      + __ldg(xw);
            float pi = gts[0][b][8 + jj]  + gts[1][b][8 + jj]  + __ldg(xw + 1024);
            float po = gts[0][b][16 + jj] + gts[1][b][16 + jj] + __ldg(xw + 2048);
            float pc = gts[0][b][24 + jj] + gts[1][b][24 + jj] + __ldg(xw + 3072);
            float f  = sigmoid_f(pf);
            float i2 = sigmoid_f(pi);
            float o  = sigmoid_f(po);
            float ct = tanh_f(pc);
            const int hidx = b * HH + j0 + jj;
            float cnew = f * __ldcg(&g_c[pb][hidx]) + i2 * ct;
            float hnew = o * tanh_f(cnew);
            __stcg(&g_c[nb][hidx], cnew);
            __stcg(&g_h[nb][hidx], hnew);
            __stcg(&g_hs[(size_t)(t * 64 + b) * HH + j0 + jj], hnew);
        }

        // ---- grid-wide barrier between timesteps ----
        grid_barrier((unsigned int)(t + 1));
    }
}

// ---------------- output projection: out[b][s][o] = hs[s][b][:] @ W_hy + b_hy ----------------
__global__ __launch_bounds__(256) void proj_kernel(const float* __restrict__ Why,
                                                   const float* __restrict__ bhy,
                                                   float* __restrict__ out) {
    __shared__ float As[16][64];
    __shared__ float Bs[16][64];
    int nt = blockIdx.x;   // 0..7
    int s  = blockIdx.y;   // 0..511
    int n0 = nt * 64;
    int tid = threadIdx.x;
    int tx = tid & 15, ty = tid >> 4;
    int ar = tid >> 2;
    int ak = (tid & 3) * 4;
    int br = tid >> 4;
    int bc4 = (tid & 15) * 4;
    const float* arow = g_hs + (size_t)(s * 64 + ar) * HH;

    float acc[4][4] = {};
    for (int k0 = 0; k0 < HH; k0 += 16) {
        float4 av = *(const float4*)(arow + k0 + ak);
        As[ak + 0][ar] = av.x; As[ak + 1][ar] = av.y;
        As[ak + 2][ar] = av.z; As[ak + 3][ar] = av.w;
        float4 bv = *(const float4*)(Why + (size_t)(k0 + br) * OO + n0 + bc4);
        *(float4*)&Bs[br][bc4] = bv;
        __syncthreads();
#pragma unroll
        for (int kk = 0; kk < 16; kk++) {
            float4 a = *(const float4*)&As[kk][ty * 4];
            float4 b = *(const float4*)&Bs[kk][tx * 4];
            float ae[4] = {a.x, a.y, a.z, a.w};
            float be[4] = {b.x, b.y, b.z, b.w};
#pragma unroll
            for (int um = 0; um < 4; um++)
#pragma unroll
                for (int un = 0; un < 4; un++)
                    acc[um][un] += ae[um] * be[un];
        }
        __syncthreads();
    }
    float4 bb = *(const float4*)(bhy + n0 + tx * 4);
#pragma unroll
    for (int um = 0; um < 4; um++) {
        int b = ty * 4 + um;
        float4 v;
        v.x = acc[um][0] + bb.x; v.y = acc[um][1] + bb.y;
        v.z = acc[um][2] + bb.z; v.w = acc[um][3] + bb.w;
        *(float4*)&out[(size_t)b * (SS * OO) + (size_t)s * OO + n0 + tx * 4] = v;
    }
}

// ---------------- copy final h, c into tail of output ----------------
__global__ void finalize_kernel(float* __restrict__ out) {
    int i = blockIdx.x * blockDim.x + threadIdx.x;
    const size_t base = (size_t)BB * SS * OO;   // 16777216
    if (i < BB * HH) {
        out[base + i]            = g_h[0][i];   // after 512 steps state is in buffer 0
        out[base + BB * HH + i]  = g_c[0][i];
    }
}

// ---------------- launch ----------------
extern "C" void kernel_launch(void* const* d_in, const int* in_sizes, int n_in,
                              void* d_out, int out_size) {
    const float* x   = (const float*)d_in[0];
    const float* h0  = (const float*)d_in[1];
    const float* c0  = (const float*)d_in[2];
    const float* Wf  = (const float*)d_in[3];
    const float* bf  = (const float*)d_in[4];
    const float* Wi  = (const float*)d_in[5];
    const float* bi  = (const float*)d_in[6];
    const float* Wo  = (const float*)d_in[7];
    const float* bo  = (const float*)d_in[8];
    const float* Wc  = (const float*)d_in[9];
    const float* bc  = (const float*)d_in[10];
    const float* Why = (const float*)d_in[11];
    const float* bhy = (const float*)d_in[12];
    float* out = (float*)d_out;

    repack_kernel<<<(128 * 1024 * 32 + 255) / 256, 256>>>(Wf, Wi, Wo, Wc);
    init_kernel<<<(BB * HH + 255) / 256, 256>>>(h0, c0);
    xw_kernel<<<dim3(64, 512), 256>>>(x, Wf, bf, Wi, bi, Wo, bo, Wc, bc);
    lstm_persist_kernel<<<NBLK, 256>>>();
    proj_kernel<<<dim3(8, 512), 256>>>(Why, bhy, out);
    finalize_kernel<<<(BB * HH + 255) / 256, 256>>>(out);
}

// round 5
// speedup vs baseline: 2.4657x; 1.8877x over previous
#include <cuda_runtime.h>
#include <cuda_bf16.h>
#include <math.h>
#include <stdint.h>

#define BB 64
#define SS 512
#define II 512
#define HH 1024
#define OO 512
#define G4 4096
#define NBLK 128        // persistent recurrence blocks (32 gate-rows each)

// ---------------- scratch (device globals; no allocation APIs) ----------------
__device__ float g_xW[(size_t)SS * BB * G4];          // [t][b][4096] x-part of gates + bias
__device__ float g_hs[(size_t)SS * BB * HH];          // [t][b][1024] h history (fp32)
__device__ float g_c[BB * HH];                        // cell state (block-owned, in place)
__device__ __nv_bfloat16 g_h_hi[2][BB * HH];          // ping-pong h bf16 hi
__device__ __nv_bfloat16 g_h_lo[2][BB * HH];          // ping-pong h bf16 lo
__device__ __nv_bfloat16 g_w_hi[(size_t)G4 * HH];     // [m][k] reordered W^T hi
__device__ __nv_bfloat16 g_w_lo[(size_t)G4 * HH];     // [m][k] reordered W^T lo
__device__ unsigned int g_bar_arrive;
__device__ unsigned int g_bar_gen;

// ---------------- smem layout for persistent kernel ----------------
#define WPAD   2064                      // 1024*2 + 16 (ldmatrix conflict-free)
#define SM_W_HI 0
#define SM_W_LO (32 * WPAD)              // 66048
#define SM_H    (2 * 32 * WPAD)          // 132096
#define HPAD    272                      // 128*2 + 16
#define HPLANE  (64 * HPAD)              // 17408
#define HBUFSZ  (2 * HPLANE)             // 34816 (hi + lo)
#define SM_GTS  (SM_H + 2 * HBUFSZ)      // 201728
#define SM_TOTAL (SM_GTS + 32 * 66 * 4)  // 210176

// ---------------- PTX helpers (sm_100-legal: cp.async / ldmatrix / mma.sync) ----------------
__device__ __forceinline__ uint32_t smem_u32(const void* p) {
    uint32_t a;
    asm("{ .reg .u64 t; cvta.to.shared.u64 t, %1; cvt.u32.u64 %0, t; }" : "=r"(a) : "l"(p));
    return a;
}
#define CP_ASYNC16(dst, src) \
    asm volatile("cp.async.cg.shared.global [%0], [%1], 16;" :: "r"(dst), "l"(src) : "memory")
#define CP_COMMIT() asm volatile("cp.async.commit_group;" ::: "memory")
#define CP_WAIT0()  asm volatile("cp.async.wait_group 0;" ::: "memory")

#define LDSM_X4(r0, r1, r2, r3, addr) \
    asm volatile("ldmatrix.sync.aligned.m8n8.x4.shared.b16 {%0,%1,%2,%3}, [%4];" \
                 : "=r"(r0), "=r"(r1), "=r"(r2), "=r"(r3) : "r"(addr))

#define MMA16816(d0, d1, d2, d3, a0, a1, a2, a3, b0, b1) \
    asm volatile("mma.sync.aligned.m16n8k16.row.col.f32.bf16.bf16.f32 " \
                 "{%0,%1,%2,%3}, {%4,%5,%6,%7}, {%8,%9}, {%0,%1,%2,%3};" \
                 : "+f"(d0), "+f"(d1), "+f"(d2), "+f"(d3) \
                 : "r"(a0), "r"(a1), "r"(a2), "r"(a3), "r"(b0), "r"(b1))

// ---------------- math helpers ----------------
__device__ __forceinline__ float sigmoid_f(float x) { return 1.0f / (1.0f + expf(-x)); }
__device__ __forceinline__ float tanh_f(float x)    { return 2.0f / (1.0f + expf(-2.0f * x)) - 1.0f; }

// ---------------- repack W^T (recurrent rows) into reordered split-bf16 ----------------
// g_w[m][k] = W_g[k][j]; m = (j>>3)*32 + g*8 + (j&7)  (f/i/o/c for same j grouped)
__global__ void repack_bf16_kernel(const float* __restrict__ Wf, const float* __restrict__ Wi,
                                   const float* __restrict__ Wo, const float* __restrict__ Wc) {
    __shared__ float tile[32][33];
    int g = blockIdx.z;
    const float* W = (g == 0) ? Wf : (g == 1) ? Wi : (g == 2) ? Wo : Wc;
    int j0 = blockIdx.x * 32, k0 = blockIdx.y * 32;
    int tx = threadIdx.x, ty = threadIdx.y;
#pragma unroll
    for (int r = 0; r < 4; r++) {
        int kk = ty + r * 8;
        tile[kk][tx] = W[(size_t)(k0 + kk) * HH + j0 + tx];
    }
    __syncthreads();
#pragma unroll
    for (int r = 0; r < 4; r++) {
        int jl = ty + r * 8;
        int j = j0 + jl;
        int m = (j >> 3) * 32 + g * 8 + (j & 7);
        float w = tile[tx][jl];
        __nv_bfloat16 hi = __float2bfloat16(w);
        __nv_bfloat16 lo = __float2bfloat16(w - __bfloat162float(hi));
        g_w_hi[(size_t)m * HH + k0 + tx] = hi;
        g_w_lo[(size_t)m * HH + k0 + tx] = lo;
    }
}

// ---------------- init ----------------
__global__ void init_kernel(const float* __restrict__ h0, const float* __restrict__ c0) {
    int i = blockIdx.x * blockDim.x + threadIdx.x;
    if (i < BB * HH) {
        g_c[i] = c0[i];
        float h = h0[i];
        __nv_bfloat16 hi = __float2bfloat16(h);
        g_h_hi[0][i] = hi;
        g_h_lo[0][i] = __float2bfloat16(h - __bfloat162float(hi));
    }
    if (i == 0) { g_bar_arrive = 0u; g_bar_gen = 0u; }
}

// ---------------- x-contribution GEMM (fp32, known-good) ----------------
__global__ __launch_bounds__(256) void xw_kernel(
    const float* __restrict__ x,
    const float* __restrict__ Wf, const float* __restrict__ bf,
    const float* __restrict__ Wi, const float* __restrict__ bi,
    const float* __restrict__ Wo, const float* __restrict__ bo,
    const float* __restrict__ Wc, const float* __restrict__ bc) {
    __shared__ float As[16][64];
    __shared__ float Bs[16][64];
    int nt = blockIdx.x;
    int t  = blockIdx.y;
    int n0 = nt * 64;
    int g  = n0 >> 10;
    int j0 = n0 & (HH - 1);
    const float* W    = (g == 0) ? Wf : (g == 1) ? Wi : (g == 2) ? Wo : Wc;
    const float* bias = (g == 0) ? bf : (g == 1) ? bi : (g == 2) ? bo : bc;
    int tid = threadIdx.x;
    int tx = tid & 15, ty = tid >> 4;
    int ar = tid >> 2, ak = (tid & 3) * 4;
    int br = tid >> 4, bc4 = (tid & 15) * 4;
    const float* xrow = x + (size_t)ar * (SS * II) + (size_t)t * II;
    float acc[4][4] = {};
    for (int k0 = 0; k0 < II; k0 += 16) {
        float4 av = *(const float4*)(xrow + k0 + ak);
        As[ak + 0][ar] = av.x; As[ak + 1][ar] = av.y; As[ak + 2][ar] = av.z; As[ak + 3][ar] = av.w;
        float4 bv = *(const float4*)(W + (size_t)(HH + k0 + br) * HH + j0 + bc4);
        *(float4*)&Bs[br][bc4] = bv;
        __syncthreads();
#pragma unroll
        for (int kk = 0; kk < 16; kk++) {
            float4 a = *(const float4*)&As[kk][ty * 4];
            float4 b = *(const float4*)&Bs[kk][tx * 4];
            float ae[4] = {a.x, a.y, a.z, a.w};
            float be[4] = {b.x, b.y, b.z, b.w};
#pragma unroll
            for (int um = 0; um < 4; um++)
#pragma unroll
                for (int un = 0; un < 4; un++) acc[um][un] += ae[um] * be[un];
        }
        __syncthreads();
    }
    float4 bb = *(const float4*)(bias + j0 + tx * 4);
#pragma unroll
    for (int um = 0; um < 4; um++) {
        int m = t * 64 + ty * 4 + um;
        float4 v;
        v.x = acc[um][0] + bb.x; v.y = acc[um][1] + bb.y;
        v.z = acc[um][2] + bb.z; v.w = acc[um][3] + bb.w;
        *(float4*)&g_xW[(size_t)m * G4 + n0 + tx * 4] = v;
    }
}

// ---------------- grid barrier ----------------
__device__ __forceinline__ void grid_barrier(unsigned int target) {
    __threadfence();
    __syncthreads();
    if (threadIdx.x == 0) {
        unsigned int old = atomicAdd(&g_bar_arrive, 1u);
        if (old == NBLK - 1) {
            atomicExch(&g_bar_arrive, 0u);
            __threadfence();
            atomicExch(&g_bar_gen, target);
        } else {
            while (atomicAdd(&g_bar_gen, 0u) < target) { __nanosleep(32); }
        }
    }
    __syncthreads();
}

// ---------------- h chunk loader: global (L2) -> smem via cp.async ----------------
__device__ __forceinline__ void load_hchunk(uint32_t sb, int buf, int c, int tid,
                                            const __nv_bfloat16* Hh, const __nv_bfloat16* Hl) {
    uint32_t base = sb + SM_H + buf * HBUFSZ;
#pragma unroll
    for (int i = 0; i < 4; i++) {
        int id = tid + i * 256;          // 0..1023
        int row = id >> 4, seg = id & 15;
        uint32_t d = base + row * HPAD + seg * 16;
        const char* sh = (const char*)Hh + (size_t)row * 2048 + c * 256 + seg * 16;
        const char* sl = (const char*)Hl + (size_t)row * 2048 + c * 256 + seg * 16;
        CP_ASYNC16(d, sh);
        CP_ASYNC16(d + HPLANE, sl);
    }
}

// ---------------- persistent split-bf16 mma.sync LSTM recurrence ----------------
// 128 blocks x 256 threads (8 warps). Block owns gate-rows [blk*32, blk*32+32)
// = hidden units j in [blk*8, blk*8+8) x 4 gates. W slice resident in smem.
// Per step: gates[32,64] = Wslice[32,1024] @ h[64,1024]^T via 3-pass split-bf16.
__global__ __launch_bounds__(256, 1) void lstm_persist_mma() {
    extern __shared__ char smem[];
    uint32_t sb = smem_u32(smem);
    const int tid  = threadIdx.x;
    const int wid  = tid >> 5;
    const int lane = tid & 31;
    const int blk  = blockIdx.x;

    // ---- load resident W slice (hi+lo), once ----
    {
        const char* srcH = (const char*)g_w_hi + ((size_t)blk * 32) * 2048;
        const char* srcL = (const char*)g_w_lo + ((size_t)blk * 32) * 2048;
        for (int i = tid; i < 4096; i += 256) {
            int row = i >> 7, seg = i & 127;
            uint32_t dst = sb + SM_W_HI + row * WPAD + seg * 16;
            CP_ASYNC16(dst, srcH + (size_t)row * 2048 + seg * 16);
            CP_ASYNC16(dst + (SM_W_LO - SM_W_HI), srcL + (size_t)row * 2048 + seg * 16);
        }
        CP_COMMIT();
        CP_WAIT0();
        __syncthreads();
    }

    // ---- per-lane ldmatrix base offsets ----
    const int mw = (wid & 1) * 16;       // warp's M offset (0/16)
    const int nw = (wid >> 1) * 16;      // warp's N offset (0/16/32/48)
    const int li = lane >> 3, lr = lane & 7;
    // A tiles: m0..7/k0:8, m8..15/k0:8, m0..7/k8:16, m8..15/k8:16
    const uint32_t aRow  = (uint32_t)(mw + ((li & 1) << 3) + lr);
    const uint32_t aKoff = (uint32_t)((li >> 1) << 3);
    const uint32_t aHi = sb + SM_W_HI + aRow * WPAD + aKoff * 2;
    const uint32_t aLo = aHi + (SM_W_LO - SM_W_HI);
    // B tiles: n0..7/k0:8, n0..7/k8:16, n8..15/k0:8, n8..15/k8:16
    const uint32_t bRow  = (uint32_t)(nw + ((li >> 1) << 3) + lr);
    const uint32_t bKoff = (uint32_t)((li & 1) << 3);
    const uint32_t bOff  = bRow * HPAD + bKoff * 2;

    float* gts = (float*)(smem + SM_GTS);
    const int j0 = blk * 8;
    const int dr = lane >> 2, dc = (lane & 3) << 1;

    for (int t = 0; t < SS; t++) {
        const int hb = t & 1, nb2 = hb ^ 1;
        const __nv_bfloat16* Hh = g_h_hi[hb];
        const __nv_bfloat16* Hl = g_h_lo[hb];

        float d0[4] = {0.f, 0.f, 0.f, 0.f};   // n-tile 0 (nw + 0..7)
        float d1[4] = {0.f, 0.f, 0.f, 0.f};   // n-tile 1 (nw + 8..15)

        load_hchunk(sb, 0, 0, tid, Hh, Hl);
        CP_COMMIT();

        for (int c = 0; c < 8; c++) {
            CP_WAIT0();          // chunk c landed
            __syncthreads();     // visible to all; all warps done with prev buffer
            if (c < 8 - 1) {
                load_hchunk(sb, (c + 1) & 1, c + 1, tid, Hh, Hl);
                CP_COMMIT();
            }
            const uint32_t hbuf = sb + SM_H + (c & 1) * HBUFSZ;
#pragma unroll
            for (int k16 = 0; k16 < 8; k16++) {
                const uint32_t ao = (uint32_t)(c * 256 + k16 * 32);
                const uint32_t bo = bOff + (uint32_t)(k16 * 32);
                uint32_t a0, a1, a2, a3, e0, e1, e2, e3;
                uint32_t b0, b1, b2, b3, f0, f1, f2, f3;
                LDSM_X4(a0, a1, a2, a3, aHi + ao);
                LDSM_X4(e0, e1, e2, e3, aLo + ao);
                LDSM_X4(b0, b1, b2, b3, hbuf + bo);            // B hi
                LDSM_X4(f0, f1, f2, f3, hbuf + HPLANE + bo);   // B lo
                MMA16816(d0[0], d0[1], d0[2], d0[3], a0, a1, a2, a3, b0, b1);
                MMA16816(d1[0], d1[1], d1[2], d1[3], a0, a1, a2, a3, b2, b3);
                MMA16816(d0[0], d0[1], d0[2], d0[3], a0, a1, a2, a3, f0, f1);
                MMA16816(d1[0], d1[1], d1[2], d1[3], a0, a1, a2, a3, f2, f3);
                MMA16816(d0[0], d0[1], d0[2], d0[3], e0, e1, e2, e3, b0, b1);
                MMA16816(d1[0], d1[1], d1[2], d1[3], e0, e1, e2, e3, b2, b3);
            }
        }

        // ---- stage D fragments to smem gts[m][b] (stride 66) ----
        // D frag: rows mw+dr (+8), cols nw + nt*8 + dc (+1)
        gts[(mw + dr) * 66 + nw + dc]          = d0[0];
        gts[(mw + dr) * 66 + nw + dc + 1]      = d0[1];
        gts[(mw + dr + 8) * 66 + nw + dc]      = d0[2];
        gts[(mw + dr + 8) * 66 + nw + dc + 1]  = d0[3];
        gts[(mw + dr) * 66 + nw + 8 + dc]      = d1[0];
        gts[(mw + dr) * 66 + nw + 8 + dc + 1]  = d1[1];
        gts[(mw + dr + 8) * 66 + nw + 8 + dc]     = d1[2];
        gts[(mw + dr + 8) * 66 + nw + 8 + dc + 1] = d1[3];
        __syncthreads();

        // ---- fused LSTM elementwise: 512 elements (64 b x 8 j) ----
        for (int it = tid; it < 512; it += 256) {
            const int b = it >> 3, jj = it & 7;
            const int j = j0 + jj;
            const float* xw = g_xW + (size_t)(t * 64 + b) * G4 + j;
            float pf = gts[(jj)      * 66 + b] + __ldg(xw);
            float pi = gts[(8 + jj)  * 66 + b] + __ldg(xw + 1024);
            float po = gts[(16 + jj) * 66 + b] + __ldg(xw + 2048);
            float pc = gts[(24 + jj) * 66 + b] + __ldg(xw + 3072);
            float f  = sigmoid_f(pf);
            float i2 = sigmoid_f(pi);
            float o  = sigmoid_f(po);
            float ct = tanh_f(pc);
            const int hidx = b * HH + j;
            float cnew = f * g_c[hidx] + i2 * ct;
            float hnew = o * tanh_f(cnew);
            g_c[hidx] = cnew;
            g_hs[(size_t)(t * 64 + b) * HH + j] = hnew;
            __nv_bfloat16 hh = __float2bfloat16(hnew);
            __stcg(&g_h_hi[nb2][hidx], hh);
            __stcg(&g_h_lo[nb2][hidx], __float2bfloat16(hnew - __bfloat162float(hh)));
        }

        grid_barrier((unsigned int)(t + 1));
    }
}

// ---------------- output projection (fp32, known-good) ----------------
__global__ __launch_bounds__(256) void proj_kernel(const float* __restrict__ Why,
                                                   const float* __restrict__ bhy,
                                                   float* __restrict__ out) {
    __shared__ float As[16][64];
    __shared__ float Bs[16][64];
    int nt = blockIdx.x;
    int s  = blockIdx.y;
    int n0 = nt * 64;
    int tid = threadIdx.x;
    int tx = tid & 15, ty = tid >> 4;
    int ar = tid >> 2, ak = (tid & 3) * 4;
    int br = tid >> 4, bc4 = (tid & 15) * 4;
    const float* arow = g_hs + (size_t)(s * 64 + ar) * HH;
    float acc[4][4] = {};
    for (int k0 = 0; k0 < HH; k0 += 16) {
        float4 av = *(const float4*)(arow + k0 + ak);
        As[ak + 0][ar] = av.x; As[ak + 1][ar] = av.y; As[ak + 2][ar] = av.z; As[ak + 3][ar] = av.w;
        float4 bv = *(const float4*)(Why + (size_t)(k0 + br) * OO + n0 + bc4);
        *(float4*)&Bs[br][bc4] = bv;
        __syncthreads();
#pragma unroll
        for (int kk = 0; kk < 16; kk++) {
            float4 a = *(const float4*)&As[kk][ty * 4];
            float4 b = *(const float4*)&Bs[kk][tx * 4];
            float ae[4] = {a.x, a.y, a.z, a.w};
            float be[4] = {b.x, b.y, b.z, b.w};
#pragma unroll
            for (int um = 0; um < 4; um++)
#pragma unroll
                for (int un = 0; un < 4; un++) acc[um][un] += ae[um] * be[un];
        }
        __syncthreads();
    }
    float4 bb = *(const float4*)(bhy + n0 + tx * 4);
#pragma unroll
    for (int um = 0; um < 4; um++) {
        int b = ty * 4 + um;
        float4 v;
        v.x = acc[um][0] + bb.x; v.y = acc[um][1] + bb.y;
        v.z = acc[um][2] + bb.z; v.w = acc[um][3] + bb.w;
        *(float4*)&out[(size_t)b * (SS * OO) + (size_t)s * OO + n0 + tx * 4] = v;
    }
}

// ---------------- finalize: h_n from g_hs[t=511], c_n from g_c ----------------
__global__ void finalize_kernel(float* __restrict__ out) {
    int i = blockIdx.x * blockDim.x + threadIdx.x;
    const size_t base = (size_t)BB * SS * OO;
    if (i < BB * HH) {
        int b = i >> 10, j = i & 1023;
        out[base + i]           = g_hs[(size_t)(511 * 64 + b) * HH + j];
        out[base + BB * HH + i] = g_c[i];
    }
}

// ---------------- launch ----------------
extern "C" void kernel_launch(void* const* d_in, const int* in_sizes, int n_in,
                              void* d_out, int out_size) {
    const float* x   = (const float*)d_in[0];
    const float* h0  = (const float*)d_in[1];
    const float* c0  = (const float*)d_in[2];
    const float* Wf  = (const float*)d_in[3];
    const float* bf  = (const float*)d_in[4];
    const float* Wi  = (const float*)d_in[5];
    const float* bi  = (const float*)d_in[6];
    const float* Wo  = (const float*)d_in[7];
    const float* bo  = (const float*)d_in[8];
    const float* Wc  = (const float*)d_in[9];
    const float* bc  = (const float*)d_in[10];
    const float* Why = (const float*)d_in[11];
    const float* bhy = (const float*)d_in[12];
    float* out = (float*)d_out;

    cudaFuncSetAttribute(lstm_persist_mma, cudaFuncAttributeMaxDynamicSharedMemorySize, SM_TOTAL);

    repack_bf16_kernel<<<dim3(32, 32, 4), dim3(32, 8)>>>(Wf, Wi, Wo, Wc);
    init_kernel<<<(BB * HH + 255) / 256, 256>>>(h0, c0);
    xw_kernel<<<dim3(64, 512), 256>>>(x, Wf, bf, Wi, bi, Wo, bo, Wc, bc);
    lstm_persist_mma<<<NBLK, 256, SM_TOTAL>>>();
    proj_kernel<<<dim3(8, 512), 256>>>(Why, bhy, out);
    finalize_kernel<<<(BB * HH + 255) / 256, 256>>>(out);
}

// round 10
// speedup vs baseline: 3.0293x; 1.2286x over previous
#include <cuda_runtime.h>
#include <cuda_bf16.h>
#include <math.h>
#include <stdint.h>

#define BB 64
#define SS 512
#define II 512
#define HH 1024
#define OO 512
#define G4 4096
#define NBLK 128        // persistent recurrence blocks (32 gate-rows each)

// ---------------- scratch (device globals; no allocation APIs) ----------------
__device__ float g_xW[(size_t)SS * BB * G4];          // [t][b][4096] x-part of gates + bias
__device__ float g_c[BB * HH];                        // cell state (block-owned, in place)
__device__ __nv_bfloat16 g_hs_hi[(size_t)SS * BB * HH];  // [t*64+b][1024] h history hi
__device__ __nv_bfloat16 g_hs_lo[(size_t)SS * BB * HH];  // [t*64+b][1024] h history lo
__device__ __nv_bfloat16 g_h_hi[2][BB * HH];          // ping-pong h bf16 hi
__device__ __nv_bfloat16 g_h_lo[2][BB * HH];          // ping-pong h bf16 lo
__device__ __nv_bfloat16 g_w_hi[(size_t)G4 * HH];     // [m][k] reordered recurrent W^T hi
__device__ __nv_bfloat16 g_w_lo[(size_t)G4 * HH];     // [m][k] reordered recurrent W^T lo
__device__ __nv_bfloat16 g_x_hi[(size_t)SS * BB * II];   // [t*64+b][512] x hi
__device__ __nv_bfloat16 g_x_lo[(size_t)SS * BB * II];
__device__ __nv_bfloat16 g_wx_hi[(size_t)G4 * II];    // [n=g*1024+j][512] x-weight hi
__device__ __nv_bfloat16 g_wx_lo[(size_t)G4 * II];
__device__ __nv_bfloat16 g_why_hi[(size_t)OO * HH];   // [o][1024] Why^T hi
__device__ __nv_bfloat16 g_why_lo[(size_t)OO * HH];
__device__ float g_bias4[G4];                         // concatenated gate biases
__device__ unsigned int g_bar_arrive;
__device__ unsigned int g_bar_gen;

// ---------------- smem layout for persistent kernel (also proj GEMM) ----------------
#define WPAD   2064
#define SM_W_HI 0
#define SM_W_LO (32 * WPAD)
#define SM_H    (2 * 32 * WPAD)
#define HPAD    272
#define HPLANE  (64 * HPAD)
#define HBUFSZ  (2 * HPLANE)
#define SM_GTS  (SM_H + 2 * HBUFSZ)
#define SM_TOTAL (SM_GTS + 32 * 66 * 4)

// ---------------- smem layout for xw GEMM (K=512 resident weights) ----------------
#define XWPAD     1040                   // 512 bf16 = 1024B + 16 pad
#define XW_W_LOOFF (32 * XWPAD)          // 33280
#define XW_H      (2 * 32 * XWPAD)       // 66560
#define XW_GTS    (XW_H + 2 * HBUFSZ)    // 136192
#define XW_TOTAL  (XW_GTS + 32 * 66 * 4) // 144640

// ---------------- PTX helpers ----------------
__device__ __forceinline__ uint32_t smem_u32(const void* p) {
    uint32_t a;
    asm("{ .reg .u64 t; cvta.to.shared.u64 t, %1; cvt.u32.u64 %0, t; }" : "=r"(a) : "l"(p));
    return a;
}
#define CP_ASYNC16(dst, src) \
    asm volatile("cp.async.cg.shared.global [%0], [%1], 16;" :: "r"(dst), "l"(src) : "memory")
#define CP_COMMIT() asm volatile("cp.async.commit_group;" ::: "memory")
#define CP_WAIT0()  asm volatile("cp.async.wait_group 0;" ::: "memory")

#define LDSM_X4(r0, r1, r2, r3, addr) \
    asm volatile("ldmatrix.sync.aligned.m8n8.x4.shared.b16 {%0,%1,%2,%3}, [%4];" \
                 : "=r"(r0), "=r"(r1), "=r"(r2), "=r"(r3) : "r"(addr))

#define MMA16816(d, a0, a1, a2, a3, b0, b1) \
    asm volatile("mma.sync.aligned.m16n8k16.row.col.f32.bf16.bf16.f32 " \
                 "{%0,%1,%2,%3}, {%4,%5,%6,%7}, {%8,%9}, {%0,%1,%2,%3};" \
                 : "+f"((d)[0]), "+f"((d)[1]), "+f"((d)[2]), "+f"((d)[3]) \
                 : "r"(a0), "r"(a1), "r"(a2), "r"(a3), "r"(b0), "r"(b1))

// ---------------- math helpers ----------------
__device__ __forceinline__ float sigmoid_f(float x) { return 1.0f / (1.0f + expf(-x)); }
__device__ __forceinline__ float tanh_f(float x)    { return 2.0f / (1.0f + expf(-2.0f * x)) - 1.0f; }

// ---------------- repack recurrent W^T into reordered split-bf16 ----------------
__global__ void repack_bf16_kernel(const float* __restrict__ Wf, const float* __restrict__ Wi,
                                   const float* __restrict__ Wo, const float* __restrict__ Wc) {
    __shared__ float tile[32][33];
    int g = blockIdx.z;
    const float* W = (g == 0) ? Wf : (g == 1) ? Wi : (g == 2) ? Wo : Wc;
    int j0 = blockIdx.x * 32, k0 = blockIdx.y * 32;
    int tx = threadIdx.x, ty = threadIdx.y;
#pragma unroll
    for (int r = 0; r < 4; r++) {
        int kk = ty + r * 8;
        tile[kk][tx] = W[(size_t)(k0 + kk) * HH + j0 + tx];
    }
    __syncthreads();
#pragma unroll
    for (int r = 0; r < 4; r++) {
        int jl = ty + r * 8;
        int j = j0 + jl;
        int m = (j >> 3) * 32 + g * 8 + (j & 7);
        float w = tile[tx][jl];
        __nv_bfloat16 hi = __float2bfloat16(w);
        __nv_bfloat16 lo = __float2bfloat16(w - __bfloat162float(hi));
        g_w_hi[(size_t)m * HH + k0 + tx] = hi;
        g_w_lo[(size_t)m * HH + k0 + tx] = lo;
    }
}

// ---------------- repack x-part weights + bias ----------------
__global__ void repack_wx_kernel(const float* __restrict__ Wf, const float* __restrict__ bf,
                                 const float* __restrict__ Wi, const float* __restrict__ bi,
                                 const float* __restrict__ Wo, const float* __restrict__ bo,
                                 const float* __restrict__ Wc, const float* __restrict__ bc) {
    __shared__ float tile[32][33];
    int g = blockIdx.z;
    const float* W    = (g == 0) ? Wf : (g == 1) ? Wi : (g == 2) ? Wo : Wc;
    const float* bias = (g == 0) ? bf : (g == 1) ? bi : (g == 2) ? bo : bc;
    int j0 = blockIdx.x * 32, k0 = blockIdx.y * 32;
    int tx = threadIdx.x, ty = threadIdx.y;
#pragma unroll
    for (int r = 0; r < 4; r++) {
        int kk = ty + r * 8;
        tile[kk][tx] = W[(size_t)(HH + k0 + kk) * HH + j0 + tx];
    }
    __syncthreads();
#pragma unroll
    for (int r = 0; r < 4; r++) {
        int jl = ty + r * 8;
        int n = g * 1024 + j0 + jl;
        float w = tile[tx][jl];
        __nv_bfloat16 hi = __float2bfloat16(w);
        __nv_bfloat16 lo = __float2bfloat16(w - __bfloat162float(hi));
        g_wx_hi[(size_t)n * II + k0 + tx] = hi;
        g_wx_lo[(size_t)n * II + k0 + tx] = lo;
        if (blockIdx.y == 0 && tx == 0) g_bias4[n] = bias[j0 + jl];
    }
}

// ---------------- repack Why^T ----------------
__global__ void repack_why_kernel(const float* __restrict__ Why) {
    __shared__ float tile[32][33];
    int o0 = blockIdx.x * 32, h0 = blockIdx.y * 32;
    int tx = threadIdx.x, ty = threadIdx.y;
#pragma unroll
    for (int r = 0; r < 4; r++) {
        int hh = ty + r * 8;
        tile[hh][tx] = Why[(size_t)(h0 + hh) * OO + o0 + tx];
    }
    __syncthreads();
#pragma unroll
    for (int r = 0; r < 4; r++) {
        int ol = ty + r * 8;
        float w = tile[tx][ol];
        __nv_bfloat16 hi = __float2bfloat16(w);
        __nv_bfloat16 lo = __float2bfloat16(w - __bfloat162float(hi));
        g_why_hi[(size_t)(o0 + ol) * HH + h0 + tx] = hi;
        g_why_lo[(size_t)(o0 + ol) * HH + h0 + tx] = lo;
    }
}

// ---------------- convert + transpose x: [b][t][k] -> [t*64+b][k] split bf16 ----------------
__global__ void convert_x_kernel(const float* __restrict__ x) {
    int i = blockIdx.x * blockDim.x + threadIdx.x;
    if (i >= BB * SS * II) return;
    int k = i & (II - 1);
    int t = (i >> 9) & (SS - 1);
    int b = i >> 18;
    float v = x[i];
    __nv_bfloat16 hi = __float2bfloat16(v);
    size_t o = ((size_t)(t * 64 + b)) * II + k;
    g_x_hi[o] = hi;
    g_x_lo[o] = __float2bfloat16(v - __bfloat162float(hi));
}

// ---------------- init ----------------
__global__ void init_kernel(const float* __restrict__ h0, const float* __restrict__ c0) {
    int i = blockIdx.x * blockDim.x + threadIdx.x;
    if (i < BB * HH) {
        g_c[i] = c0[i];
        float h = h0[i];
        __nv_bfloat16 hi = __float2bfloat16(h);
        g_h_hi[0][i] = hi;
        g_h_lo[0][i] = __float2bfloat16(h - __bfloat162float(hi));
    }
    if (i == 0) { g_bar_arrive = 0u; g_bar_gen = 0u; }
}

// ---------------- grid barrier ----------------
__device__ __forceinline__ void grid_barrier(unsigned int target) {
    __threadfence();
    __syncthreads();
    if (threadIdx.x == 0) {
        unsigned int old = atomicAdd(&g_bar_arrive, 1u);
        if (old == NBLK - 1) {
            atomicExch(&g_bar_arrive, 0u);
            __threadfence();
            atomicExch(&g_bar_gen, target);
        } else {
            while (atomicAdd(&g_bar_gen, 0u) < target) { __nanosleep(32); }
        }
    }
    __syncthreads();
}

// ---------------- stream chunk loader: 64 rows x 128 k-cols (hi+lo planes) ----------------
// Identical structure to the proven load_hchunk; row stride is a runtime arg.
__device__ __forceinline__ void load_stream64(uint32_t dstbase,
                                              const __nv_bfloat16* Sh, const __nv_bfloat16* Sl,
                                              size_t row0, int c, int tid, int rowbytes) {
#pragma unroll
    for (int i = 0; i < 4; i++) {
        int id = tid + i * 256;
        int row = id >> 4, seg = id & 15;
        uint32_t d = dstbase + row * HPAD + seg * 16;
        size_t s = (row0 + (size_t)row) * (size_t)rowbytes + (size_t)(c * 256 + seg * 16);
        CP_ASYNC16(d, (const char*)Sh + s);
        CP_ASYNC16(d + HPLANE, (const char*)Sl + s);
    }
}

// ---------------- h chunk loader (recurrence; verbatim from R5) ----------------
__device__ __forceinline__ void load_hchunk(uint32_t sb, int buf, int c, int tid,
                                            const __nv_bfloat16* Hh, const __nv_bfloat16* Hl) {
    uint32_t base = sb + SM_H + buf * HBUFSZ;
#pragma unroll
    for (int i = 0; i < 4; i++) {
        int id = tid + i * 256;
        int row = id >> 4, seg = id & 15;
        uint32_t d = base + row * HPAD + seg * 16;
        const char* sh = (const char*)Hh + (size_t)row * 2048 + c * 256 + seg * 16;
        const char* sl = (const char*)Hl + (size_t)row * 2048 + c * 256 + seg * 16;
        CP_ASYNC16(d, sh);
        CP_ASYNC16(d + HPLANE, sl);
    }
}

// ---------------- xw GEMM: clone of one recurrence timestep, looped over x-row groups ----------------
// C[32 gate-cols][64 x-rows] per iteration; resident A = 32 wx rows (K=512);
// streamed B = x rows. grid (128 n-tiles, 16 m-groups), 256 threads.
__global__ __launch_bounds__(256, 1) void xw_mma_kernel() {
    extern __shared__ char smem[];
    uint32_t sb = smem_u32(smem);
    const int tid  = threadIdx.x;
    const int wid  = tid >> 5;
    const int lane = tid & 31;
    const int n0 = blockIdx.x * 32;                 // gate-col tile
    const size_t mg = (size_t)blockIdx.y * 2048;    // x-row group base

    // resident Wx slice (hi+lo) + first stream chunk, one commit
    {
        const char* srcH = (const char*)g_wx_hi + (size_t)n0 * 1024;
        const char* srcL = (const char*)g_wx_lo + (size_t)n0 * 1024;
        for (int i = tid; i < 2048; i += 256) {
            int row = i >> 6, seg = i & 63;
            uint32_t dst = sb + row * XWPAD + seg * 16;
            CP_ASYNC16(dst, srcH + (size_t)row * 1024 + seg * 16);
            CP_ASYNC16(dst + XW_W_LOOFF, srcL + (size_t)row * 1024 + seg * 16);
        }
    }
    load_stream64(sb + XW_H, g_x_hi, g_x_lo, mg, 0, tid, 1024);
    CP_COMMIT();

    const int mw = (wid & 1) * 16;
    const int nw = (wid >> 1) * 16;
    const int li = lane >> 3, lr = lane & 7;
    const uint32_t aRow  = (uint32_t)(mw + ((li & 1) << 3) + lr);
    const uint32_t aKoff = (uint32_t)((li >> 1) << 3);
    const uint32_t aHi = sb + aRow * XWPAD + aKoff * 2;
    const uint32_t aLo = aHi + XW_W_LOOFF;
    const uint32_t bRow  = (uint32_t)(nw + ((li >> 1) << 3) + lr);
    const uint32_t bKoff = (uint32_t)((li & 1) << 3);
    const uint32_t bOff  = bRow * HPAD + bKoff * 2;

    float* gts = (float*)(smem + XW_GTS);
    const int dr = lane >> 2, dc = (lane & 3) << 1;

    float d0[4] = {0.f, 0.f, 0.f, 0.f};
    float d1[4] = {0.f, 0.f, 0.f, 0.f};

    for (int ch = 0; ch < 128; ch++) {              // 32 m-iters x 4 K-chunks
        CP_WAIT0();
        __syncthreads();
        if (ch + 1 < 128) {
            load_stream64(sb + XW_H + ((ch + 1) & 1) * HBUFSZ, g_x_hi, g_x_lo,
                          mg + (size_t)((ch + 1) >> 2) * 64, (ch + 1) & 3, tid, 1024);
            CP_COMMIT();
        }
        const uint32_t hbuf = sb + XW_H + (ch & 1) * HBUFSZ;
        const uint32_t cbytes = (uint32_t)((ch & 3) * 256);
#pragma unroll
        for (int k16 = 0; k16 < 8; k16++) {
            const uint32_t ao = cbytes + (uint32_t)(k16 * 32);
            const uint32_t bo = bOff + (uint32_t)(k16 * 32);
            uint32_t a0, a1, a2, a3, e0, e1, e2, e3;
            uint32_t b0, b1, b2, b3, f0, f1, f2, f3;
            LDSM_X4(a0, a1, a2, a3, aHi + ao);
            LDSM_X4(e0, e1, e2, e3, aLo + ao);
            LDSM_X4(b0, b1, b2, b3, hbuf + bo);
            LDSM_X4(f0, f1, f2, f3, hbuf + HPLANE + bo);
            MMA16816(d0, a0, a1, a2, a3, b0, b1);
            MMA16816(d1, a0, a1, a2, a3, b2, b3);
            MMA16816(d0, a0, a1, a2, a3, f0, f1);
            MMA16816(d1, a0, a1, a2, a3, f2, f3);
            MMA16816(d0, e0, e1, e2, e3, b0, b1);
            MMA16816(d1, e0, e1, e2, e3, b2, b3);
        }
        if ((ch & 3) == 3) {
            gts[(mw + dr) * 66 + nw + dc]             = d0[0];
            gts[(mw + dr) * 66 + nw + dc + 1]         = d0[1];
            gts[(mw + dr + 8) * 66 + nw + dc]         = d0[2];
            gts[(mw + dr + 8) * 66 + nw + dc + 1]     = d0[3];
            gts[(mw + dr) * 66 + nw + 8 + dc]         = d1[0];
            gts[(mw + dr) * 66 + nw + 8 + dc + 1]     = d1[1];
            gts[(mw + dr + 8) * 66 + nw + 8 + dc]     = d1[2];
            gts[(mw + dr + 8) * 66 + nw + 8 + dc + 1] = d1[3];
            __syncthreads();
            const size_t mrow = mg + (size_t)(ch >> 2) * 64;
            for (int it = tid; it < 2048; it += 256) {
                int jj = it & 31, b = it >> 5;
                float v = gts[jj * 66 + b] + g_bias4[n0 + jj];
                g_xW[(mrow + (size_t)b) * G4 + n0 + jj] = v;
            }
            __syncthreads();
            d0[0] = 0.f; d0[1] = 0.f; d0[2] = 0.f; d0[3] = 0.f;
            d1[0] = 0.f; d1[1] = 0.f; d1[2] = 0.f; d1[3] = 0.f;
        }
    }
}

// ---------------- proj GEMM: same clone with K=1024, recurrence smem layout ----------------
// C[32 o-cols][64 hs-rows] per iteration. grid (16 n-tiles, 16 m-groups), 256 threads.
__global__ __launch_bounds__(256, 1) void proj_mma_kernel(const float* __restrict__ bhy,
                                                          float* __restrict__ out) {
    extern __shared__ char smem[];
    uint32_t sb = smem_u32(smem);
    const int tid  = threadIdx.x;
    const int wid  = tid >> 5;
    const int lane = tid & 31;
    const int n0 = blockIdx.x * 32;                 // output-col tile
    const size_t mg = (size_t)blockIdx.y * 2048;    // hs-row group base

    // resident Why slice (hi+lo) + first stream chunk
    {
        const char* srcH = (const char*)g_why_hi + (size_t)n0 * 2048;
        const char* srcL = (const char*)g_why_lo + (size_t)n0 * 2048;
        for (int i = tid; i < 4096; i += 256) {
            int row = i >> 7, seg = i & 127;
            uint32_t dst = sb + SM_W_HI + row * WPAD + seg * 16;
            CP_ASYNC16(dst, srcH + (size_t)row * 2048 + seg * 16);
            CP_ASYNC16(dst + (SM_W_LO - SM_W_HI), srcL + (size_t)row * 2048 + seg * 16);
        }
    }
    load_stream64(sb + SM_H, g_hs_hi, g_hs_lo, mg, 0, tid, 2048);
    CP_COMMIT();

    const int mw = (wid & 1) * 16;
    const int nw = (wid >> 1) * 16;
    const int li = lane >> 3, lr = lane & 7;
    const uint32_t aRow  = (uint32_t)(mw + ((li & 1) << 3) + lr);
    const uint32_t aKoff = (uint32_t)((li >> 1) << 3);
    const uint32_t aHi = sb + SM_W_HI + aRow * WPAD + aKoff * 2;
    const uint32_t aLo = aHi + (SM_W_LO - SM_W_HI);
    const uint32_t bRow  = (uint32_t)(nw + ((li >> 1) << 3) + lr);
    const uint32_t bKoff = (uint32_t)((li & 1) << 3);
    const uint32_t bOff  = bRow * HPAD + bKoff * 2;

    float* gts = (float*)(smem + SM_GTS);
    const int dr = lane >> 2, dc = (lane & 3) << 1;

    float d0[4] = {0.f, 0.f, 0.f, 0.f};
    float d1[4] = {0.f, 0.f, 0.f, 0.f};

    for (int ch = 0; ch < 256; ch++) {              // 32 m-iters x 8 K-chunks
        CP_WAIT0();
        __syncthreads();
        if (ch + 1 < 256) {
            load_stream64(sb + SM_H + ((ch + 1) & 1) * HBUFSZ, g_hs_hi, g_hs_lo,
                          mg + (size_t)((ch + 1) >> 3) * 64, (ch + 1) & 7, tid, 2048);
            CP_COMMIT();
        }
        const uint32_t hbuf = sb + SM_H + (ch & 1) * HBUFSZ;
        const uint32_t cbytes = (uint32_t)((ch & 7) * 256);
#pragma unroll
        for (int k16 = 0; k16 < 8; k16++) {
            const uint32_t ao = cbytes + (uint32_t)(k16 * 32);
            const uint32_t bo = bOff + (uint32_t)(k16 * 32);
            uint32_t a0, a1, a2, a3, e0, e1, e2, e3;
            uint32_t b0, b1, b2, b3, f0, f1, f2, f3;
            LDSM_X4(a0, a1, a2, a3, aHi + ao);
            LDSM_X4(e0, e1, e2, e3, aLo + ao);
            LDSM_X4(b0, b1, b2, b3, hbuf + bo);
            LDSM_X4(f0, f1, f2, f3, hbuf + HPLANE + bo);
            MMA16816(d0, a0, a1, a2, a3, b0, b1);
            MMA16816(d1, a0, a1, a2, a3, b2, b3);
            MMA16816(d0, a0, a1, a2, a3, f0, f1);
            MMA16816(d1, a0, a1, a2, a3, f2, f3);
            MMA16816(d0, e0, e1, e2, e3, b0, b1);
            MMA16816(d1, e0, e1, e2, e3, b2, b3);
        }
        if ((ch & 7) == 7) {
            gts[(mw + dr) * 66 + nw + dc]             = d0[0];
            gts[(mw + dr) * 66 + nw + dc + 1]         = d0[1];
            gts[(mw + dr + 8) * 66 + nw + dc]         = d0[2];
            gts[(mw + dr + 8) * 66 + nw + dc + 1]     = d0[3];
            gts[(mw + dr) * 66 + nw + 8 + dc]         = d1[0];
            gts[(mw + dr) * 66 + nw + 8 + dc + 1]     = d1[1];
            gts[(mw + dr + 8) * 66 + nw + 8 + dc]     = d1[2];
            gts[(mw + dr + 8) * 66 + nw + 8 + dc + 1] = d1[3];
            __syncthreads();
            const size_t mrow = mg + (size_t)(ch >> 3) * 64;
            for (int it = tid; it < 2048; it += 256) {
                int jj = it & 31, b = it >> 5;
                float v = gts[jj * 66 + b] + bhy[n0 + jj];
                size_t r = mrow + (size_t)b;
                int s = (int)(r >> 6);
                int bb = (int)(r & 63);
                out[(size_t)bb * (SS * OO) + (size_t)s * OO + n0 + jj] = v;
            }
            __syncthreads();
            d0[0] = 0.f; d0[1] = 0.f; d0[2] = 0.f; d0[3] = 0.f;
            d1[0] = 0.f; d1[1] = 0.f; d1[2] = 0.f; d1[3] = 0.f;
        }
    }
}

// ---------------- persistent split-bf16 mma.sync LSTM recurrence (R5-proven) ----------------
__global__ __launch_bounds__(256, 1) void lstm_persist_mma() {
    extern __shared__ char smem[];
    uint32_t sb = smem_u32(smem);
    const int tid  = threadIdx.x;
    const int wid  = tid >> 5;
    const int lane = tid & 31;
    const int blk  = blockIdx.x;

    // resident W slice
    {
        const char* srcH = (const char*)g_w_hi + ((size_t)blk * 32) * 2048;
        const char* srcL = (const char*)g_w_lo + ((size_t)blk * 32) * 2048;
        for (int i = tid; i < 4096; i += 256) {
            int row = i >> 7, seg = i & 127;
            uint32_t dst = sb + SM_W_HI + row * WPAD + seg * 16;
            CP_ASYNC16(dst, srcH + (size_t)row * 2048 + seg * 16);
            CP_ASYNC16(dst + (SM_W_LO - SM_W_HI), srcL + (size_t)row * 2048 + seg * 16);
        }
        CP_COMMIT();
        CP_WAIT0();
        __syncthreads();
    }

    const int mw = (wid & 1) * 16;
    const int nw = (wid >> 1) * 16;
    const int li = lane >> 3, lr = lane & 7;
    const uint32_t aRow  = (uint32_t)(mw + ((li & 1) << 3) + lr);
    const uint32_t aKoff = (uint32_t)((li >> 1) << 3);
    const uint32_t aHi = sb + SM_W_HI + aRow * WPAD + aKoff * 2;
    const uint32_t aLo = aHi + (SM_W_LO - SM_W_HI);
    const uint32_t bRow  = (uint32_t)(nw + ((li >> 1) << 3) + lr);
    const uint32_t bKoff = (uint32_t)((li & 1) << 3);
    const uint32_t bOff  = bRow * HPAD + bKoff * 2;

    float* gts = (float*)(smem + SM_GTS);
    const int j0 = blk * 8;
    const int dr = lane >> 2, dc = (lane & 3) << 1;

    for (int t = 0; t < SS; t++) {
        const int hb = t & 1, nb2 = hb ^ 1;
        const __nv_bfloat16* Hh = g_h_hi[hb];
        const __nv_bfloat16* Hl = g_h_lo[hb];

        float d0[4] = {0.f, 0.f, 0.f, 0.f};
        float d1[4] = {0.f, 0.f, 0.f, 0.f};

        load_hchunk(sb, 0, 0, tid, Hh, Hl);
        CP_COMMIT();

        for (int c = 0; c < 8; c++) {
            CP_WAIT0();
            __syncthreads();
            if (c < 7) {
                load_hchunk(sb, (c + 1) & 1, c + 1, tid, Hh, Hl);
                CP_COMMIT();
            }
            const uint32_t hbuf = sb + SM_H + (c & 1) * HBUFSZ;
#pragma unroll
            for (int k16 = 0; k16 < 8; k16++) {
                const uint32_t ao = (uint32_t)(c * 256 + k16 * 32);
                const uint32_t bo = bOff + (uint32_t)(k16 * 32);
                uint32_t a0, a1, a2, a3, e0, e1, e2, e3;
                uint32_t b0, b1, b2, b3, f0, f1, f2, f3;
                LDSM_X4(a0, a1, a2, a3, aHi + ao);
                LDSM_X4(e0, e1, e2, e3, aLo + ao);
                LDSM_X4(b0, b1, b2, b3, hbuf + bo);
                LDSM_X4(f0, f1, f2, f3, hbuf + HPLANE + bo);
                MMA16816(d0, a0, a1, a2, a3, b0, b1);
                MMA16816(d1, a0, a1, a2, a3, b2, b3);
                MMA16816(d0, a0, a1, a2, a3, f0, f1);
                MMA16816(d1, a0, a1, a2, a3, f2, f3);
                MMA16816(d0, e0, e1, e2, e3, b0, b1);
                MMA16816(d1, e0, e1, e2, e3, b2, b3);
            }
        }

        gts[(mw + dr) * 66 + nw + dc]             = d0[0];
        gts[(mw + dr) * 66 + nw + dc + 1]         = d0[1];
        gts[(mw + dr + 8) * 66 + nw + dc]         = d0[2];
        gts[(mw + dr + 8) * 66 + nw + dc + 1]     = d0[3];
        gts[(mw + dr) * 66 + nw + 8 + dc]         = d1[0];
        gts[(mw + dr) * 66 + nw + 8 + dc + 1]     = d1[1];
        gts[(mw + dr + 8) * 66 + nw + 8 + dc]     = d1[2];
        gts[(mw + dr + 8) * 66 + nw + 8 + dc + 1] = d1[3];
        __syncthreads();

        for (int it = tid; it < 512; it += 256) {
            const int b = it >> 3, jj = it & 7;
            const int j = j0 + jj;
            const float* xw = g_xW + (size_t)(t * 64 + b) * G4 + j;
            float pf = gts[(jj)      * 66 + b] + __ldg(xw);
            float pi = gts[(8 + jj)  * 66 + b] + __ldg(xw + 1024);
            float po = gts[(16 + jj) * 66 + b] + __ldg(xw + 2048);
            float pc = gts[(24 + jj) * 66 + b] + __ldg(xw + 3072);
            float f  = sigmoid_f(pf);
            float i2 = sigmoid_f(pi);
            float o  = sigmoid_f(po);
            float ct = tanh_f(pc);
            const int hidx = b * HH + j;
            float cnew = f * g_c[hidx] + i2 * ct;
            float hnew = o * tanh_f(cnew);
            g_c[hidx] = cnew;
            __nv_bfloat16 hh = __float2bfloat16(hnew);
            __nv_bfloat16 hl = __float2bfloat16(hnew - __bfloat162float(hh));
            const size_t hsidx = (size_t)(t * 64 + b) * HH + j;
            g_hs_hi[hsidx] = hh;
            g_hs_lo[hsidx] = hl;
            __stcg(&g_h_hi[nb2][hidx], hh);
            __stcg(&g_h_lo[nb2][hidx], hl);
        }

        grid_barrier((unsigned int)(t + 1));
    }
}

// ---------------- finalize: h_n = hs(t=511) reconstructed, c_n = g_c ----------------
__global__ void finalize_kernel(float* __restrict__ out) {
    int i = blockIdx.x * blockDim.x + threadIdx.x;
    const size_t base = (size_t)BB * SS * OO;
    if (i < BB * HH) {
        int b = i >> 10, j = i & 1023;
        size_t hsidx = (size_t)(511 * 64 + b) * HH + j;
        out[base + i] = __bfloat162float(g_hs_hi[hsidx]) + __bfloat162float(g_hs_lo[hsidx]);
        out[base + BB * HH + i] = g_c[i];
    }
}

// ---------------- launch ----------------
extern "C" void kernel_launch(void* const* d_in, const int* in_sizes, int n_in,
                              void* d_out, int out_size) {
    const float* x   = (const float*)d_in[0];
    const float* h0  = (const float*)d_in[1];
    const float* c0  = (const float*)d_in[2];
    const float* Wf  = (const float*)d_in[3];
    const float* bf  = (const float*)d_in[4];
    const float* Wi  = (const float*)d_in[5];
    const float* bi  = (const float*)d_in[6];
    const float* Wo  = (const float*)d_in[7];
    const float* bo  = (const float*)d_in[8];
    const float* Wc  = (const float*)d_in[9];
    const float* bc  = (const float*)d_in[10];
    const float* Why = (const float*)d_in[11];
    const float* bhy = (const float*)d_in[12];
    float* out = (float*)d_out;

    cudaFuncSetAttribute(lstm_persist_mma, cudaFuncAttributeMaxDynamicSharedMemorySize, SM_TOTAL);
    cudaFuncSetAttribute(xw_mma_kernel,   cudaFuncAttributeMaxDynamicSharedMemorySize, XW_TOTAL);
    cudaFuncSetAttribute(proj_mma_kernel, cudaFuncAttributeMaxDynamicSharedMemorySize, SM_TOTAL);

    repack_bf16_kernel<<<dim3(32, 32, 4), dim3(32, 8)>>>(Wf, Wi, Wo, Wc);
    repack_wx_kernel<<<dim3(32, 16, 4), dim3(32, 8)>>>(Wf, bf, Wi, bi, Wo, bo, Wc, bc);
    repack_why_kernel<<<dim3(16, 32), dim3(32, 8)>>>(Why);
    convert_x_kernel<<<(BB * SS * II + 255) / 256, 256>>>(x);
    init_kernel<<<(BB * HH + 255) / 256, 256>>>(h0, c0);

    // xW = x @ Wx^T + bias : 4096 gate-cols x 32768 x-rows, K=512
    xw_mma_kernel<<<dim3(128, 16), 256, XW_TOTAL>>>();

    lstm_persist_mma<<<NBLK, 256, SM_TOTAL>>>();

    // out = hs @ Why + bhy : 512 o-cols x 32768 hs-rows, K=1024
    proj_mma_kernel<<<dim3(16, 16), 256, SM_TOTAL>>>(bhy, out);

    finalize_kernel<<<(BB * HH + 255) / 256, 256>>>(out);
}